// round 7
// baseline (speedup 1.0000x reference)
#include <cuda_runtime.h>

#define BB 64
#define TT 8000
#define SS 10
#define CHUNKS 9
#define ROWSPC ((TT + CHUNKS - 1) / CHUNKS)   // 889
#define NACC 110                              // 100 sel + 10 tot
#define NWORK (BB * CHUNKS)                   // 576 pairwise blocks
#define FULL 0xFFFFFFFFu
#define FLT_MAX_C 3.402823466e+38f
#define LN2F 0.69314718055994530942f

// Scratch (no allocations allowed). Zero-initialized device globals.
__device__ float    g_part[BB * CHUNKS * NACC];
__device__ double   g_bsum[BB];
__device__ unsigned g_done[BB];
__device__ unsigned g_ticket2;

__device__ __forceinline__ unsigned enc_f32(float x) {
    unsigned b = __float_as_uint(x);
    return (b & 0x80000000u) ? ~b : (b | 0x80000000u);
}
__device__ __forceinline__ float dec_f32(unsigned e) {
    unsigned b = (e & 0x80000000u) ? (e & 0x7FFFFFFFu) : ~e;
    return __uint_as_float(b);
}

// 10-way register select, 4-deep tree (idx in 0..9).
__device__ __forceinline__ float sel10(const float w[SS], int idx) {
    const float x01 = (idx & 1) ? w[1] : w[0];
    const float x23 = (idx & 1) ? w[3] : w[2];
    const float x45 = (idx & 1) ? w[5] : w[4];
    const float x67 = (idx & 1) ? w[7] : w[6];
    const float x89 = (idx & 1) ? w[9] : w[8];
    const float y03 = (idx & 2) ? x23 : x01;
    const float y47 = (idx & 2) ? x67 : x45;
    const float z07 = (idx & 4) ? y47 : y03;
    return (idx & 8) ? x89 : z07;
}

template <int IH, int JH>
__device__ __forceinline__ void pw_body(const float* __restrict__ pred,
                                        const float* __restrict__ tgt,
                                        int b, int t0, int tend, int slot,
                                        float sel[5][5], float tot[5]) {
    for (int t = t0 + slot; t < tend; t += 64) {
        const size_t base = ((size_t)b * TT + (size_t)t) * SS;
        const float2* pp = reinterpret_cast<const float2*>(pred + base + IH * 4);
        const float2* tp = reinterpret_cast<const float2*>(tgt  + base + JH * 4);
        const float2 p0 = pp[0], p1 = pp[1], p2 = pp[2];
        const float2 q0 = tp[0], q1 = tp[1], q2 = tp[2];
        const float pe[6] = {p0.x, p0.y, p1.x, p1.y, p2.x, p2.y};
        const float te[6] = {q0.x, q0.y, q1.x, q1.y, q2.x, q2.y};

        float diff[5];
#pragma unroll
        for (int ii = 0; ii < 5; ii++) {
            const float p  = pe[ii + IH];          // static index
            const float l1 = __log2f(p);           // lg2(p)
            const float l2 = __log2f(1.0f - p);    // lg2(1-p); p in [0.01, 0.99]
            diff[ii] = l1 - l2;
            tot[ii] += l2;
        }
#pragma unroll
        for (int jj = 0; jj < 5; jj++) {
            const float tj = te[jj + JH];          // exactly 0.0f or 1.0f
#pragma unroll
            for (int ii = 0; ii < 5; ii++)
                sel[ii][jj] = fmaf(diff[ii], tj, sel[ii][jj]);
        }
    }
}

// ---------------------------------------------------------------------------
// One kernel, two block roles:
//   bid <  NWORK : pairwise chunk block (proven r6 config) + release ticket.
//   bid >= NWORK : Hungarian block for batch (bid-NWORK): spin-wait on the
//                  ticket, then warp-collective JV + fused final mean.
// Work blocks come first in bid order and 576 <= 592 wave-1 slots, so every
// work block is resident in wave 1 -> spinners can never cause deadlock.
// ---------------------------------------------------------------------------
__global__ __launch_bounds__(256, 4) void fused_kernel(const float* __restrict__ pred,
                                                       const float* __restrict__ tgt,
                                                       float* __restrict__ out) {
    const int tid  = threadIdx.x;
    const int lane = tid & 31;
    const int w    = tid >> 5;

    if (blockIdx.x < NWORK) {
        // ================= Pairwise chunk block =================
        const int b    = blockIdx.x / CHUNKS;
        const int c    = blockIdx.x % CHUNKS;
        const int slot = tid & 63;
        const int q    = w >> 1;

        const int t0   = c * ROWSPC;
        const int tend = (t0 + ROWSPC < TT) ? (t0 + ROWSPC) : TT;

        float sel[5][5];
        float tot[5];
#pragma unroll
        for (int ii = 0; ii < 5; ii++) {
            tot[ii] = 0.0f;
#pragma unroll
            for (int jj = 0; jj < 5; jj++) sel[ii][jj] = 0.0f;
        }

        switch (q) {
            case 0: pw_body<0, 0>(pred, tgt, b, t0, tend, slot, sel, tot); break;
            case 1: pw_body<1, 0>(pred, tgt, b, t0, tend, slot, sel, tot); break;
            case 2: pw_body<0, 1>(pred, tgt, b, t0, tend, slot, sel, tot); break;
            default: pw_body<1, 1>(pred, tgt, b, t0, tend, slot, sel, tot); break;
        }

#pragma unroll
        for (int ii = 0; ii < 5; ii++) {
#pragma unroll
            for (int jj = 0; jj < 5; jj++) {
                float v = sel[ii][jj];
#pragma unroll
                for (int o = 16; o; o >>= 1) v += __shfl_down_sync(FULL, v, o);
                sel[ii][jj] = v;
            }
            float v = tot[ii];
#pragma unroll
            for (int o = 16; o; o >>= 1) v += __shfl_down_sync(FULL, v, o);
            tot[ii] = v;
        }

        __shared__ float s[8][30];
        if (lane == 0) {
#pragma unroll
            for (int ii = 0; ii < 5; ii++) {
#pragma unroll
                for (int jj = 0; jj < 5; jj++) s[w][ii * 5 + jj] = sel[ii][jj];
                s[w][25 + ii] = tot[ii];
            }
        }
        __syncthreads();

        if (tid < NACC) {
            int qq, idx;
            if (tid < 100) {
                const int i = tid / 10, j = tid % 10;
                const int ih = (i >= 5), jh = (j >= 5);
                qq  = jh * 2 + ih;
                idx = (i % 5) * 5 + (j % 5);
            } else {
                const int i = tid - 100;
                const int ih = (i >= 5);
                qq  = ih;
                idx = 25 + (i % 5);
            }
            g_part[(b * CHUNKS + c) * NACC + tid] =
                (s[2 * qq][idx] + s[2 * qq + 1][idx]) * LN2F;
        }

        // Release the per-batch ticket.
        __threadfence();
        __syncthreads();
        if (tid == 0) atomicAdd(&g_done[b], 1u);
        return;
    }

    // ================= Hungarian block =================
    const int b = blockIdx.x - NWORK;
    __shared__ float s_cost[100];

    if (tid == 0) {
        unsigned done;
        while (true) {
            asm volatile("ld.acquire.gpu.global.u32 %0, [%1];"
                         : "=r"(done) : "l"(&g_done[b]) : "memory");
            if (done == CHUNKS) break;
            __nanosleep(64);
        }
        g_done[b] = 0;                 // reset for graph replay (sole consumer)
    }
    __syncthreads();

    // Cost build (threads 0..99, coalesced-ish over chunk partials).
    if (tid < 100) {
        const int i = tid / 10;
        float sl = 0.0f, to = 0.0f;
#pragma unroll
        for (int c = 0; c < CHUNKS; c++) {
            const float* gp = &g_part[(b * CHUNKS + c) * NACC];
            sl += __ldcg(&gp[tid]);
            to += __ldcg(&gp[100 + i]);
        }
        s_cost[tid] = -(to + sl) * (1.0f / (float)TT);
    }
    __syncthreads();
    if (w != 0) return;

    const bool isCol = (lane >= 1 && lane <= SS);
    const int  cl    = isCol ? (lane - 1) : 0;

    float colv[SS];
#pragma unroll
    for (int i = 0; i < SS; i++) colv[i] = s_cost[i * 10 + cl];

    // Warm start: v[j] = min_i colv; u[i] = min_j (colv[i] - v) (uniform regs).
    float v = 0.0f;
    if (isCol) {
        float mn = colv[0];
#pragma unroll
        for (int i = 1; i < SS; i++) mn = fminf(mn, colv[i]);
        v = mn;
    }
    float uu[SS];
#pragma unroll
    for (int i = 0; i < SS; i++) {
        const float t = isCol ? (colv[i] - v) : FLT_MAX_C;
        uu[i] = dec_f32(__reduce_min_sync(FULL, enc_f32(t)));
    }

    // Greedy tight-edge pre-assignment on exact-zero reduced costs.
    int p = 0, way = 0;
    unsigned rowdone = 0u;
#pragma unroll
    for (int i = 1; i <= SS; i++) {
        const float red = isCol ? ((colv[i - 1] - v) - uu[i - 1]) : 1.0f;
        const bool  z   = isCol && (p == 0) && (red == 0.0f);
        const unsigned bal = __ballot_sync(FULL, z);
        if (bal) {
            const int j = __ffs(bal) - 1;
            if (lane == j) p = i;
            rowdone |= 1u << i;
        }
    }

    // Dijkstra for each remaining free row.
    for (int root = 1; root <= SS; root++) {
        if ((rowdone >> root) & 1u) continue;
        if (lane == 0) p = root;

        float wv[SS];
#pragma unroll
        for (int i = 0; i < SS; i++)
            wv[i] = isCol ? ((colv[i] - uu[i]) - v) : FLT_MAX_C;

        float minv = FLT_MAX_C;
        unsigned used = 1u;            // virtual column 0
        unsigned rowm = 0u;
        int j0 = 0, i0 = root;

        while (true) {
            rowm |= 1u << i0;

            const bool  active = isCol && !((used >> lane) & 1u);
            const float cur    = sel10(wv, i0 - 1);
            if (active && cur < minv) { minv = cur; way = j0; }

            const unsigned key = active ? ((enc_f32(minv) & 0xFFFFFFE0u) | (unsigned)lane)
                                        : 0xFFFFFFFFu;
            const unsigned m   = __reduce_min_sync(FULL, key);
            const int      j1  = (int)(m & 31u);
            const float delta  = __shfl_sync(FULL, minv, j1);   // exact winner value
            const int   pn     = __shfl_sync(FULL, p, j1);      // next row (0 = free)

            if (isCol) {
                if ((used >> lane) & 1u) v -= delta;
                else                     minv -= delta;
            }
#pragma unroll
            for (int i = 1; i <= SS; i++)
                if ((rowm >> i) & 1u) uu[i - 1] += delta;       // uniform

            used |= 1u << j1;
            j0 = j1;
            if (pn == 0) break;
            i0 = pn;
        }

        while (j0) {
            const int jprev = __shfl_sync(FULL, way, j0);
            const int pprev = __shfl_sync(FULL, p, jprev);
            if (lane == j0) p = pprev;
            j0 = jprev;
        }
    }

    // Matched sum for this batch (exact f32 cost entries, f64 accumulate).
    double val = 0.0;
    if (isCol) val = (double)s_cost[(p - 1) * 10 + cl];
#pragma unroll
    for (int o = 16; o; o >>= 1) val += __shfl_down_sync(FULL, val, o);
    if (lane == 0) g_bsum[b] = val;

    // Fused finalize: last Hungarian block computes the mean.
    __threadfence();
    unsigned t2 = 0;
    if (lane == 0) t2 = atomicAdd(&g_ticket2, 1u);
    t2 = __shfl_sync(FULL, t2, 0);
    if (t2 == BB - 1) {
        if (lane == 0) g_ticket2 = 0;              // reset for graph replay
        __threadfence();
        double x = __ldcg(&g_bsum[lane]) + __ldcg(&g_bsum[lane + 32]);
#pragma unroll
        for (int o = 16; o; o >>= 1) x += __shfl_down_sync(FULL, x, o);
        if (lane == 0) out[0] = (float)(x / (double)(BB * SS));
    }
}

extern "C" void kernel_launch(void* const* d_in, const int* in_sizes, int n_in,
                              void* d_out, int out_size) {
    const float* pred = (const float*)d_in[0];
    const float* tgt  = (const float*)d_in[1];
    fused_kernel<<<NWORK + BB, 256>>>(pred, tgt, (float*)d_out);
}